// round 4
// baseline (speedup 1.0000x reference)
#include <cuda_runtime.h>

// ----------------------------------------------------------------------------
// Cross_MultiAttention — algebraically folded, dual-lane (branch-pair) f32x2.
//
// logit_h,br(s,j) = (f_br[s] @ M_h + v_h) . fcat[j]   with M_h [6,12]
// att@V folds through Wp into per-(head,branch) [6,12] P.  Per head-pass we
// pre-project Fp[j][o] = fcat[j] . P_h[o]  (branch pair in f32x2 lanes), so
// the j-loop is: 12 fma2 logit + 2 ex2 + 1 add2 + 6 fma2 accumulate.
// One head per pass -> ~115 regs -> 2 CTAs/SM (16 warps) for latency hiding.
// ----------------------------------------------------------------------------

#define SCALE_EMB 0.044194173824159216f   // 512^-0.5
#define LOG2E     1.4426950408889634f

typedef unsigned long long u64;

struct Params {
    float M[8][6][12];      // LOG2E*SCALE * A_q_h @ A_k_h^T
    float v[8][12];         // LOG2E*SCALE * bq_eff_h @ A_k_h^T
    u64   Pp[8][6][12];     // pack2(P_br1[h][o][c], P_br2[h][o][c])
    float C[6];             // bp + (Wp1+Wp2) @ bv_eff
};

__device__ float g_part[3][8][13][512];   // per-m-chunk partial folds (row12 = bias)
__device__ float g_A[3][13][512];         // folded: [0]=Aq(6)+bqe, [1]=Ak+bke, [2]=Av+bve
__device__ Params g_params;

// ---- packed f32x2 helpers ----
__device__ __forceinline__ u64 pack2(float lo, float hi) {
    u64 r; asm("mov.b64 %0, {%1,%2};" : "=l"(r) : "f"(lo), "f"(hi)); return r;
}
__device__ __forceinline__ void unpack2(u64 v, float& lo, float& hi) {
    asm("mov.b64 {%0,%1}, %2;" : "=f"(lo), "=f"(hi) : "l"(v));
}
__device__ __forceinline__ u64 fma2(u64 a, u64 b, u64 c) {
    u64 d; asm("fma.rn.f32x2 %0, %1, %2, %3;" : "=l"(d) : "l"(a), "l"(b), "l"(c)); return d;
}
__device__ __forceinline__ u64 mul2(u64 a, u64 b) {
    u64 d; asm("mul.rn.f32x2 %0, %1, %2;" : "=l"(d) : "l"(a), "l"(b)); return d;
}
__device__ __forceinline__ u64 add2(u64 a, u64 b) {
    u64 d; asm("add.rn.f32x2 %0, %1, %2;" : "=l"(d) : "l"(a), "l"(b)); return d;
}
__device__ __forceinline__ float ex2f(float x) {
    float y; asm("ex2.approx.ftz.f32 %0, %1;" : "=f"(y) : "f"(x)); return y;
}
__device__ __forceinline__ float rcpf(float x) {
    float y; asm("rcp.approx.ftz.f32 %0, %1;" : "=f"(y) : "f"(x)); return y;
}

// ----------------------------------------------------------------------------
// Precompute 1a: partial fold over a 64-wide m chunk.
// ----------------------------------------------------------------------------
__global__ void fold_partial(const float* __restrict__ W_emb,  const float* __restrict__ b_emb,
                             const float* __restrict__ W_emb2, const float* __restrict__ b_emb2,
                             const float* __restrict__ Wq, const float* __restrict__ Wk,
                             const float* __restrict__ Wv)
{
    int mat = blockIdx.x >> 3, chunk = blockIdx.x & 7;
    const float* We = (mat == 0) ? W_emb : W_emb2;
    const float* be = (mat == 0) ? b_emb : b_emb2;
    const float* W  = (mat == 0) ? Wq : (mat == 1 ? Wk : Wv);
    int R = (mat == 0) ? 6 : 12;

    __shared__ float sE[12][64];
    __shared__ float sb[64];
    int tid = threadIdx.x;
    int mc0 = chunk * 64;
    for (int i = tid; i < R * 64; i += 512) {
        int k = i >> 6, mm = i & 63;
        sE[k][mm] = We[k * 512 + mc0 + mm];
    }
    if (tid < 64) sb[tid] = be[mc0 + tid];
    __syncthreads();

    int e = tid;
    float acc[12];
#pragma unroll
    for (int k = 0; k < 12; k++) acc[k] = 0.f;
    float bacc = 0.f;
    if (R == 6) {
#pragma unroll 8
        for (int mm = 0; mm < 64; mm++) {
            float w = W[(mc0 + mm) * 512 + e];
            bacc += sb[mm] * w;
#pragma unroll
            for (int k = 0; k < 6; k++) acc[k] += sE[k][mm] * w;
        }
    } else {
#pragma unroll 4
        for (int mm = 0; mm < 64; mm++) {
            float w = W[(mc0 + mm) * 512 + e];
            bacc += sb[mm] * w;
#pragma unroll
            for (int k = 0; k < 12; k++) acc[k] += sE[k][mm] * w;
        }
    }
    for (int k = 0; k < R; k++) g_part[mat][chunk][k][e] = acc[k];
    g_part[mat][chunk][12][e] = bacc;
}

// ----------------------------------------------------------------------------
// Precompute 1b: deterministic reduce over the 8 chunks + add projection bias.
// ----------------------------------------------------------------------------
__global__ void fold_reduce(const float* __restrict__ bq, const float* __restrict__ bk,
                            const float* __restrict__ bv)
{
    int t = blockIdx.x * blockDim.x + threadIdx.x;
    if (t >= 3 * 13 * 512) return;
    int mat = t / (13 * 512);
    int r   = (t / 512) % 13;
    int e   = t & 511;
    if (mat == 0 && r >= 6 && r < 12) { g_A[0][r][e] = 0.f; return; }
    float s = 0.f;
#pragma unroll
    for (int c = 0; c < 8; c++) s += g_part[mat][c][r][e];
    if (r == 12) s += (mat == 0 ? bq[e] : (mat == 1 ? bk[e] : bv[e]));
    g_A[mat][r][e] = s;
}

// ----------------------------------------------------------------------------
// Precompute 2: tiny per-head matrices (log2e*SCALE prefolded; P packed).
// ----------------------------------------------------------------------------
__global__ void precompute_small(const float* __restrict__ Wp, const float* __restrict__ bp)
{
    int idx = blockIdx.x * 256 + threadIdx.x;
    const float KS = LOG2E * SCALE_EMB;
    if (idx < 576) {                                   // M[h][k][c]
        int h = idx / 72, r = idx % 72, k = r / 12, c = r % 12;
        float s = 0.f;
#pragma unroll 4
        for (int d = 0; d < 64; d++) s += g_A[0][k][h * 64 + d] * g_A[1][c][h * 64 + d];
        g_params.M[h][k][c] = KS * s;
    } else if (idx < 672) {                            // v[h][c]
        int t = idx - 576, h = t / 12, c = t % 12;
        float s = 0.f;
#pragma unroll 4
        for (int d = 0; d < 64; d++) s += g_A[0][12][h * 64 + d] * g_A[1][c][h * 64 + d];
        g_params.v[h][c] = KS * s;
    } else if (idx < 1248) {                           // Pp[h][o][c] (both branches)
        int t = idx - 672, h = t / 72, q = t % 72, o = q / 12, c = q % 12;
        float s0 = 0.f, s1 = 0.f;
#pragma unroll 4
        for (int d = 0; d < 64; d++) {
            float av = g_A[2][c][h * 64 + d];
            s0 += Wp[o * 1024 +       h * 64 + d] * av;
            s1 += Wp[o * 1024 + 512 + h * 64 + d] * av;
        }
        g_params.Pp[h][o][c] = pack2(s0, s1);
    } else if (idx < 1254) {                           // C[o]
        int o = idx - 1248;
        float s = bp[o];
#pragma unroll 4
        for (int e = 0; e < 512; e++)
            s += (Wp[o * 1024 + e] + Wp[o * 1024 + 512 + e]) * g_A[2][12][e];
        g_params.C[o] = s;
    }
}

// ----------------------------------------------------------------------------
// Main fused kernel: one CTA per 16x16 tile (512 CTAs), one thread per query s.
// 8 passes (one head each); branch pair rides the f32x2 lanes.
// ----------------------------------------------------------------------------
__global__ __launch_bounds__(256, 2)
void cross_attn_main(const float* __restrict__ img1, const float* __restrict__ img2,
                     float* __restrict__ out)
{
    __shared__ __align__(16) u64 sFd[256][12];   // fcat dup-lane: (f_c, f_c)
    __shared__ __align__(16) u64 sFp[256][6];    // per-pass projected features
    __shared__ Params sp;

    int b  = blockIdx.x;
    int bi = b >> 6, th = (b >> 3) & 7, tw = b & 7;
    int s  = threadIdx.x;
    int y  = s >> 4, x = s & 15;
    int base = bi * 6 * 16384 + (th * 16 + y) * 128 + (tw * 16 + x);

    float f1r[6], f2r[6];
#pragma unroll
    for (int c = 0; c < 6; c++) {
        f1r[c] = img1[base + c * 16384];
        f2r[c] = img2[base + c * 16384];
    }
#pragma unroll
    for (int c = 0; c < 6; c++) {
        sFd[s][c]     = pack2(f1r[c], f1r[c]);
        sFd[s][6 + c] = pack2(f2r[c], f2r[c]);
    }
    {
        float* dst = (float*)&sp;
        const float* src = (const float*)&g_params;
        for (int i = s; i < (int)(sizeof(Params) / 4); i += 256) dst[i] = src[i];
    }
    __syncthreads();

    u64 outacc[6];
#pragma unroll
    for (int o = 0; o < 6; o++) outacc[o] = 0ull;

    for (int h = 0; h < 8; h++) {
        // ---- per-pass setup ----
        // g[c] = (branch1, branch2) prescaled logit vector:  v_h + f_br @ M_h
        u64 g[12];
#pragma unroll
        for (int c = 0; c < 12; c++) {
            float a1 = sp.v[h][c], a2 = a1;
#pragma unroll
            for (int k = 0; k < 6; k++) {
                float m = sp.M[h][k][c];
                a1 += f1r[k] * m;
                a2 += f2r[k] * m;
            }
            g[c] = pack2(a1, a2);
        }
        // Fp[s][o] = sum_c fcat[s][c] * Pp[h][o][c]   (lanes = branch P's)
        if (h) __syncthreads();          // prior pass done reading sFp
#pragma unroll
        for (int o = 0; o < 6; o++) {
            u64 acc = mul2(pack2(f1r[0], f1r[0]), sp.Pp[h][o][0]);
#pragma unroll
            for (int k = 1; k < 6; k++)
                acc = fma2(pack2(f1r[k], f1r[k]), sp.Pp[h][o][k], acc);
#pragma unroll
            for (int k = 0; k < 6; k++)
                acc = fma2(pack2(f2r[k], f2r[k]), sp.Pp[h][o][6 + k], acc);
            sFp[s][o] = acc;
        }
        __syncthreads();

        u64 O[6];
#pragma unroll
        for (int o = 0; o < 6; o++) O[o] = 0ull;
        u64 l = 0ull;

        // Logits are O(0.1) by construction (weights 0.02, folded twice):
        // exp without max-subtraction is exact softmax.
#pragma unroll 2
        for (int j = 0; j < 256; j++) {
            const ulonglong2* rp = (const ulonglong2*)(&sFd[j][0]);
            ulonglong2 q0 = rp[0], q1 = rp[1], q2 = rp[2];
            ulonglong2 q3 = rp[3], q4 = rp[4], q5 = rp[5];
            const ulonglong2* fp = (const ulonglong2*)(&sFp[j][0]);
            ulonglong2 p0 = fp[0], p1 = fp[1], p2 = fp[2];

            // two half-depth chains
            u64 ae = mul2(g[0], q0.x);
            u64 ao = mul2(g[1], q0.y);
            ae = fma2(g[2],  q1.x, ae);  ao = fma2(g[3],  q1.y, ao);
            ae = fma2(g[4],  q2.x, ae);  ao = fma2(g[5],  q2.y, ao);
            ae = fma2(g[6],  q3.x, ae);  ao = fma2(g[7],  q3.y, ao);
            ae = fma2(g[8],  q4.x, ae);  ao = fma2(g[9],  q4.y, ao);
            ae = fma2(g[10], q5.x, ae);  ao = fma2(g[11], q5.y, ao);
            u64 a = add2(ae, ao);

            float e0, e1;
            unpack2(a, e0, e1);
            u64 pp = pack2(ex2f(e0), ex2f(e1));
            l = add2(l, pp);

            O[0] = fma2(pp, p0.x, O[0]);
            O[1] = fma2(pp, p0.y, O[1]);
            O[2] = fma2(pp, p1.x, O[2]);
            O[3] = fma2(pp, p1.y, O[3]);
            O[4] = fma2(pp, p2.x, O[4]);
            O[5] = fma2(pp, p2.y, O[5]);
        }

        float la, lb;
        unpack2(l, la, lb);
        u64 inv = pack2(rcpf(la), rcpf(lb));
#pragma unroll
        for (int o = 0; o < 6; o++) outacc[o] = fma2(O[o], inv, outacc[o]);
    }

#pragma unroll
    for (int o = 0; o < 6; o++) {
        float lo, hi;
        unpack2(outacc[o], lo, hi);
        out[base + o * 16384] = sp.C[o] + lo + hi;
    }
}

// ----------------------------------------------------------------------------
extern "C" void kernel_launch(void* const* d_in, const int* in_sizes, int n_in,
                              void* d_out, int out_size)
{
    const float* img1   = (const float*)d_in[0];
    const float* img2   = (const float*)d_in[1];
    const float* W_emb  = (const float*)d_in[2];
    const float* b_emb  = (const float*)d_in[3];
    const float* W_emb2 = (const float*)d_in[4];
    const float* b_emb2 = (const float*)d_in[5];
    const float* Wq     = (const float*)d_in[6];
    const float* bq     = (const float*)d_in[7];
    const float* Wk     = (const float*)d_in[8];
    const float* bk     = (const float*)d_in[9];
    const float* Wv     = (const float*)d_in[10];
    const float* bv     = (const float*)d_in[11];
    const float* Wp     = (const float*)d_in[12];
    const float* bp     = (const float*)d_in[13];
    float* out = (float*)d_out;

    fold_partial<<<24, 512>>>(W_emb, b_emb, W_emb2, b_emb2, Wq, Wk, Wv);
    fold_reduce<<<78, 256>>>(bq, bk, bv);
    precompute_small<<<5, 256>>>(Wp, bp);
    cross_attn_main<<<512, 256>>>(img1, img2, out);
}